// round 5
// baseline (speedup 1.0000x reference)
#include <cuda_runtime.h>
#include <stdint.h>

// FP32 bit-pulse -> FP8 E4M3 bit-pulse converter.
// Input:  N*32 floats, exactly 0.0/1.0, per value [S, E7..E0, M22..M0] (MSB first)
// Output: N*8  floats, per value [S, E3..E0, M2..M0]
//
// Round-5: ballot-free. Each thread owns one value and loads its 32 pulses as
// 8x LDG.128 (front-batchable vector loads -> warp MLP = 32 cache lines).
// Since pulses are exact 0.0/1.0, the IEEE word is rebuilt with FFMA-immediate
// sums (exact integers < 2^16 per half), moving all reconstruction onto the
// idle FMA pipe and eliminating the per-load VOTE serialization.

__global__ void __launch_bounds__(256)
fp32_to_fp8_pulse_kernel(const float* __restrict__ in,
                         float* __restrict__ out,
                         int nvals)
{
    const int v = blockIdx.x * blockDim.x + threadIdx.x;   // one value per thread
    if (v >= nvals) return;

    const float4* p = reinterpret_cast<const float4*>(in + (size_t)v * 32);

    // Batch all 8 vector loads (32 floats = this thread's bit pulses).
    float4 q[8];
#pragma unroll
    for (int i = 0; i < 8; i++) q[i] = __ldcs(&p[i]);

    const float* f = reinterpret_cast<const float*>(q);

    // Reconstruct IEEE fp32 word: pulse j (MSB-first) -> bit (31-j).
    // hi covers pulses 0..15 (bits 31..16), lo covers 16..31 (bits 15..0).
    // Two accumulators per half to shorten the FFMA dependency chain.
    float hi0 = 0.f, hi1 = 0.f, lo0 = 0.f, lo1 = 0.f;
#pragma unroll
    for (int j = 0; j < 8; j++) {
        hi0 = fmaf(f[j],      (float)(1u << (15 - j)), hi0);        // pulses 0..7
        hi1 = fmaf(f[j + 8],  (float)(1u << (7  - j)), hi1);        // pulses 8..15
        lo0 = fmaf(f[j + 16], (float)(1u << (15 - j)), lo0);        // pulses 16..23
        lo1 = fmaf(f[j + 24], (float)(1u << (7  - j)), lo1);        // pulses 24..31
    }
    const uint32_t hi = (uint32_t)(hi0 + hi1);
    const uint32_t lo = (uint32_t)(lo0 + lo1);
    const uint32_t word = (hi << 16) | lo;

    const uint32_t s    = word >> 31;
    const uint32_t exp  = (word >> 23) & 0xFFu;
    const uint32_t mant = word & 0x7FFFFFu;

    // ---- normal path: fp8_exp = exp - 120, RNE round 23 -> 3 mantissa bits ----
    uint32_t kept  = mant >> 20;
    uint32_t R     = (mant >> 19) & 1u;
    uint32_t S     = (mant & 0x7FFFFu) ? 1u : 0u;
    uint32_t L     = kept & 1u;
    uint32_t mr    = kept + (R & (S | L));
    uint32_t carry = mr >> 3;
    uint32_t mant_norm = carry ? 0u : (mr & 7u);
    int exp_norm = (int)exp - 120 + (int)carry;

    // ---- subnormal path (117 <= exp <= 120): shift 1.mant right, RNE ----
    uint32_t full = (1u << 23) | mant;
    int sh = 141 - (int)exp;
    sh = sh < 1 ? 1 : (sh > 24 ? 24 : sh);
    uint32_t kept_s = full >> sh;
    uint32_t Rs = (full >> (sh - 1)) & 1u;
    uint32_t Ss = (full & ((1u << (sh - 1)) - 1u)) ? 1u : 0u;
    uint32_t Ls = kept_s & 1u;
    uint32_t ms = kept_s + (Rs & (Ss | Ls));
    uint32_t sub_exp  = (ms >= 8u) ? 1u : 0u;
    uint32_t sub_mant = (ms >= 8u) ? 0u : ms;

    // ---- select overflow / subnormal / underflow / normal ----
    uint32_t exp8, mant8;
    if (exp > 134u) {
        exp8 = 15u; mant8 = 6u;
    } else if (exp >= 117u) {
        if (exp <= 120u) { exp8 = sub_exp; mant8 = sub_mant; }
        else             { exp8 = (uint32_t)exp_norm; mant8 = mant_norm; }
    } else {
        exp8 = 0u; mant8 = 0u;         // underflow
    }

    // ---- emit 8 bit-pulses: [S, E3..E0, M2..M0] ----
    float4 o0 = make_float4((float)s,
                            (float)((exp8 >> 3) & 1u),
                            (float)((exp8 >> 2) & 1u),
                            (float)((exp8 >> 1) & 1u));
    float4 o1 = make_float4((float)(exp8 & 1u),
                            (float)((mant8 >> 2) & 1u),
                            (float)((mant8 >> 1) & 1u),
                            (float)(mant8 & 1u));

    float4* op = reinterpret_cast<float4*>(out + (size_t)v * 8);
    __stcs(&op[0], o0);    // streaming store: lane writes one full 32B sector
    __stcs(&op[1], o1);
}

extern "C" void kernel_launch(void* const* d_in, const int* in_sizes, int n_in,
                              void* d_out, int out_size)
{
    const float* in  = (const float*)d_in[0];
    float*       out = (float*)d_out;
    const int nvals  = in_sizes[0] / 32;       // 2,097,152

    const int threads = 256;
    const int blocks = (nvals + threads - 1) / threads;

    fp32_to_fp8_pulse_kernel<<<blocks, threads>>>(in, out, nvals);
}

// round 6
// speedup vs baseline: 1.0874x; 1.0874x over previous
#include <cuda_runtime.h>
#include <stdint.h>

// FP32 bit-pulse -> FP8 E4M3 bit-pulse converter.
// Input:  N*32 floats, exactly 0.0/1.0, per value [S, E7..E0, M22..M0] (MSB first)
// Output: N*8  floats, per value [S, E3..E0, M2..M0]
//
// Round-6: smem-transpose. Each warp owns a 32-value tile (1024 floats):
//   phase 1: 8 fully-coalesced LDG.128 rounds (each warp instr = 4 fully
//            consumed 128B lines -> minimal L1 wavefronts, high MLP since
//            LDG->STS staging is front-batched by ptxas)
//   phase 2: STS.128 into a warp-private smem slice, padded stride 36 floats
//            (conflict-free for both store and load phases)
//   phase 3: __syncwarp; each thread reads its value's 32 pulses via LDS.128
//   phase 4: FFMA-immediate word reconstruction (pulses are exact 0/1),
//            integer E4M3 conversion, 2x STG.128 streaming stores.
// No ballots (no VOTE serialization), no bar.sync.

#define VSTRIDE 36   // floats per value row in smem (32 + 4 pad)

__global__ void __launch_bounds__(256)
fp32_to_fp8_pulse_kernel(const float* __restrict__ in,
                         float* __restrict__ out,
                         int nvals)
{
    __shared__ float sm[8][32 * VSTRIDE];    // 8 warps * 32 values * 36 floats = 36 KB

    const int lane = threadIdx.x & 31;
    const int wrp  = threadIdx.x >> 5;
    const int tile = blockIdx.x * 8 + wrp;   // 32-value tile index
    const int base = tile * 32;              // first value of this warp's tile
    if (base >= nvals) return;

    const float4* in4 = reinterpret_cast<const float4*>(in) + (size_t)base * 8;
    float* smw = sm[wrp];

    // Phase 1: 8 coalesced vector loads (front-batched -> 32 lines in flight/warp).
    float4 q[8];
#pragma unroll
    for (int i = 0; i < 8; i++) q[i] = __ldcs(&in4[i * 32 + lane]);

    // Phase 2: scatter to smem, transposed to value-major with padded stride.
    // Loaded float4 #i of this lane is global float4 (i*32 + lane) of the tile:
    // it belongs to value u = (i*32+lane)>>3 at float offset o = ((i*32+lane)&7)*4.
#pragma unroll
    for (int i = 0; i < 8; i++) {
        int idx = i * 32 + lane;
        int u = idx >> 3;
        int o = (idx & 7) << 2;
        *reinterpret_cast<float4*>(&smw[u * VSTRIDE + o]) = q[i];
    }
    __syncwarp();

    // Phase 3: each thread gathers its own value's 32 pulses (conflict-free).
    float f[32];
#pragma unroll
    for (int i = 0; i < 8; i++) {
        float4 t = *reinterpret_cast<const float4*>(&smw[lane * VSTRIDE + i * 4]);
        f[i * 4 + 0] = t.x; f[i * 4 + 1] = t.y; f[i * 4 + 2] = t.z; f[i * 4 + 3] = t.w;
    }

    // Phase 4a: reconstruct IEEE fp32 word. Pulse j (MSB-first) -> bit (31-j).
    // Exact integer sums < 2^16 per half; FFMA-immediate on the idle fma pipe.
    float hi0 = 0.f, hi1 = 0.f, lo0 = 0.f, lo1 = 0.f;
#pragma unroll
    for (int j = 0; j < 8; j++) {
        hi0 = fmaf(f[j],      (float)(1u << (15 - j)), hi0);   // pulses 0..7
        hi1 = fmaf(f[j + 8],  (float)(1u << (7  - j)), hi1);   // pulses 8..15
        lo0 = fmaf(f[j + 16], (float)(1u << (15 - j)), lo0);   // pulses 16..23
        lo1 = fmaf(f[j + 24], (float)(1u << (7  - j)), lo1);   // pulses 24..31
    }
    const uint32_t hi = (uint32_t)(hi0 + hi1);
    const uint32_t lo = (uint32_t)(lo0 + lo1);
    const uint32_t word = (hi << 16) | lo;

    const uint32_t s    = word >> 31;
    const uint32_t exp  = (word >> 23) & 0xFFu;
    const uint32_t mant = word & 0x7FFFFFu;

    // ---- normal path: fp8_exp = exp - 120, RNE round 23 -> 3 mantissa bits ----
    uint32_t kept  = mant >> 20;
    uint32_t R     = (mant >> 19) & 1u;
    uint32_t S     = (mant & 0x7FFFFu) ? 1u : 0u;
    uint32_t L     = kept & 1u;
    uint32_t mr    = kept + (R & (S | L));
    uint32_t carry = mr >> 3;
    uint32_t mant_norm = carry ? 0u : (mr & 7u);
    int exp_norm = (int)exp - 120 + (int)carry;

    // ---- subnormal path (117 <= exp <= 120): shift 1.mant right, RNE ----
    uint32_t full = (1u << 23) | mant;
    int sh = 141 - (int)exp;
    sh = sh < 1 ? 1 : (sh > 24 ? 24 : sh);
    uint32_t kept_s = full >> sh;
    uint32_t Rs = (full >> (sh - 1)) & 1u;
    uint32_t Ss = (full & ((1u << (sh - 1)) - 1u)) ? 1u : 0u;
    uint32_t Ls = kept_s & 1u;
    uint32_t ms = kept_s + (Rs & (Ss | Ls));
    uint32_t sub_exp  = (ms >= 8u) ? 1u : 0u;
    uint32_t sub_mant = (ms >= 8u) ? 0u : ms;

    // ---- select overflow / subnormal / underflow / normal ----
    uint32_t exp8, mant8;
    if (exp > 134u) {
        exp8 = 15u; mant8 = 6u;
    } else if (exp >= 117u) {
        if (exp <= 120u) { exp8 = sub_exp; mant8 = sub_mant; }
        else             { exp8 = (uint32_t)exp_norm; mant8 = mant_norm; }
    } else {
        exp8 = 0u; mant8 = 0u;         // underflow
    }

    // ---- emit 8 bit-pulses: [S, E3..E0, M2..M0] ----
    float4 o0 = make_float4((float)s,
                            (float)((exp8 >> 3) & 1u),
                            (float)((exp8 >> 2) & 1u),
                            (float)((exp8 >> 1) & 1u));
    float4 o1 = make_float4((float)(exp8 & 1u),
                            (float)((mant8 >> 2) & 1u),
                            (float)((mant8 >> 1) & 1u),
                            (float)(mant8 & 1u));

    float4* op = reinterpret_cast<float4*>(out + (size_t)(base + lane) * 8);
    __stcs(&op[0], o0);
    __stcs(&op[1], o1);
}

extern "C" void kernel_launch(void* const* d_in, const int* in_sizes, int n_in,
                              void* d_out, int out_size)
{
    const float* in  = (const float*)d_in[0];
    float*       out = (float*)d_out;
    const int nvals  = in_sizes[0] / 32;       // 2,097,152

    const int threads = 256;                   // 8 warps, 32 values per warp
    const int blocks = (nvals + threads - 1) / threads;

    fp32_to_fp8_pulse_kernel<<<blocks, threads>>>(in, out, nvals);
}